// round 3
// baseline (speedup 1.0000x reference)
#include <cuda_runtime.h>
#include <cstdint>
#include <cmath>

#define NB 32
#define FEAT 320
#define NPTS 2048

// scratch: qT(20971520) kT(20971520) vT(20971520) attn(3276800) tmp(20971520)
static __device__ float g_scratch[87162880];
#define OFF_QT 0LL
#define OFF_KT 20971520LL
#define OFF_VT 41943040LL
#define OFF_AT 62914560LL
#define OFF_TMP 66191360LL

__device__ __forceinline__ uint32_t f2tf32(float f) {
    uint32_t u;
    asm("cvt.rna.tf32.f32 %0, %1;" : "=r"(u) : "f"(f));
    return u;
}

__device__ __forceinline__ void mma_tf32(float* d, const uint32_t* a, const uint32_t* b) {
    asm volatile(
        "mma.sync.aligned.m16n8k8.row.col.f32.tf32.tf32.f32 "
        "{%0,%1,%2,%3}, {%4,%5,%6,%7}, {%8,%9}, {%0,%1,%2,%3};"
        : "+f"(d[0]), "+f"(d[1]), "+f"(d[2]), "+f"(d[3])
        : "r"(a[0]), "r"(a[1]), "r"(a[2]), "r"(a[3]), "r"(b[0]), "r"(b[1]));
}

// C[M,N] = alpha * A[M,K](row-major, lda) * B (col: B[k + n*ldb], row: B[k*ldb + n]) (+ D)
// Block tile 64 x BN, BK=16, 256 threads, warps 2x4, warp tile 32 x (BN/4).
template<int BN, bool BROW>
__global__ __launch_bounds__(256)
void gemm_tf32_kernel(const float* __restrict__ Ag, const float* __restrict__ Bg,
                      float* __restrict__ Cg, const float* __restrict__ Dg,
                      int K, int lda, int ldb, int ldc,
                      long long sA, long long sB, long long sC, long long sD,
                      float alpha)
{
    constexpr int BM = 64, BK = 16;
    constexpr int TN = BN / 4;       // warp n-tile
    constexpr int NI = TN / 8;       // n8 subtiles per warp
    constexpr int BLD = BN / 64;     // float4 B loads per thread

    __shared__ uint32_t As[2][BM][20];   // [m][k], pad 20 -> conflict-free frag loads
    __shared__ uint32_t Bs[2][BN][20];   // [n][k], pad 20

    const int tid  = threadIdx.x;
    const int lane = tid & 31;
    const int warp = tid >> 5;
    const int wm = warp & 1;
    const int wn = warp >> 1;
    const int bz = blockIdx.z;
    const int bm = blockIdx.y * BM;
    const int bn = blockIdx.x * BN;

    const float* A = Ag + (long long)bz * sA;
    const float* B = Bg + (long long)bz * sB;
    float*       C = Cg + (long long)bz * sC;
    const float* D = Dg ? (Dg + (long long)bz * sD) : nullptr;

    float acc[2][NI][4];
#pragma unroll
    for (int i = 0; i < 2; i++)
#pragma unroll
        for (int j = 0; j < NI; j++)
#pragma unroll
            for (int r = 0; r < 4; r++) acc[i][j][r] = 0.f;

    const int arow = tid >> 2;          // 0..63
    const int akc  = (tid & 3) << 2;    // 0,4,8,12

    float4 ra;
    float4 rb[BLD];

    auto LDG_TILES = [&](int k0) {
        ra = *reinterpret_cast<const float4*>(A + (long long)(bm + arow) * lda + k0 + akc);
        if (!BROW) {
#pragma unroll
            for (int j = 0; j < BLD; j++) {
                int idx = tid + j * 256;
                int n = idx >> 2, kc = (idx & 3) << 2;
                rb[j] = *reinterpret_cast<const float4*>(B + (long long)(bn + n) * ldb + k0 + kc);
            }
        } else {
#pragma unroll
            for (int j = 0; j < BLD; j++) {
                int idx = tid + j * 256;
                int k = idx / (BN / 4), nc = (idx % (BN / 4)) << 2;
                rb[j] = *reinterpret_cast<const float4*>(B + (long long)(k0 + k) * ldb + bn + nc);
            }
        }
    };

    auto STS_TILES = [&](int buf) {
        As[buf][arow][akc + 0] = f2tf32(ra.x);
        As[buf][arow][akc + 1] = f2tf32(ra.y);
        As[buf][arow][akc + 2] = f2tf32(ra.z);
        As[buf][arow][akc + 3] = f2tf32(ra.w);
        if (!BROW) {
#pragma unroll
            for (int j = 0; j < BLD; j++) {
                int idx = tid + j * 256;
                int n = idx >> 2, kc = (idx & 3) << 2;
                Bs[buf][n][kc + 0] = f2tf32(rb[j].x);
                Bs[buf][n][kc + 1] = f2tf32(rb[j].y);
                Bs[buf][n][kc + 2] = f2tf32(rb[j].z);
                Bs[buf][n][kc + 3] = f2tf32(rb[j].w);
            }
        } else {
#pragma unroll
            for (int j = 0; j < BLD; j++) {
                int idx = tid + j * 256;
                int k = idx / (BN / 4), nc = (idx % (BN / 4)) << 2;
                Bs[buf][nc + 0][k] = f2tf32(rb[j].x);
                Bs[buf][nc + 1][k] = f2tf32(rb[j].y);
                Bs[buf][nc + 2][k] = f2tf32(rb[j].z);
                Bs[buf][nc + 3][k] = f2tf32(rb[j].w);
            }
        }
    };

    auto COMPUTE = [&](int buf) {
#pragma unroll
        for (int kk = 0; kk < 2; kk++) {
            uint32_t a[2][4];
            uint32_t bf[NI][2];
#pragma unroll
            for (int mi = 0; mi < 2; mi++) {
                int r = wm * 32 + mi * 16 + (lane >> 2);
                int c = kk * 8 + (lane & 3);
                a[mi][0] = As[buf][r][c];
                a[mi][1] = As[buf][r + 8][c];
                a[mi][2] = As[buf][r][c + 4];
                a[mi][3] = As[buf][r + 8][c + 4];
            }
#pragma unroll
            for (int ni = 0; ni < NI; ni++) {
                int n = wn * TN + ni * 8 + (lane >> 2);
                int c = kk * 8 + (lane & 3);
                bf[ni][0] = Bs[buf][n][c];
                bf[ni][1] = Bs[buf][n][c + 4];
            }
#pragma unroll
            for (int mi = 0; mi < 2; mi++)
#pragma unroll
                for (int ni = 0; ni < NI; ni++)
                    mma_tf32(acc[mi][ni], a[mi], bf[ni]);
        }
    };

    LDG_TILES(0);
    STS_TILES(0);
    __syncthreads();
    int buf = 0;
    for (int k0 = 0;;) {
        bool nxt = (k0 + BK) < K;
        if (nxt) LDG_TILES(k0 + BK);
        COMPUTE(buf);
        if (!nxt) break;
        STS_TILES(buf ^ 1);
        __syncthreads();
        buf ^= 1;
        k0 += BK;
    }

    // epilogue
#pragma unroll
    for (int mi = 0; mi < 2; mi++) {
#pragma unroll
        for (int ni = 0; ni < NI; ni++) {
            int row = bm + wm * 32 + mi * 16 + (lane >> 2);
            int col = bn + wn * TN + ni * 8 + ((lane & 3) << 1);
            long long i0 = (long long)row * ldc + col;
            long long i1 = i0 + 8LL * ldc;
            float v0 = alpha * acc[mi][ni][0];
            float v1 = alpha * acc[mi][ni][1];
            float v2 = alpha * acc[mi][ni][2];
            float v3 = alpha * acc[mi][ni][3];
            if (D) { v0 += D[i0]; v1 += D[i0 + 1]; v2 += D[i1]; v3 += D[i1 + 1]; }
            C[i0] = v0; C[i0 + 1] = v1; C[i1] = v2; C[i1 + 1] = v3;
        }
    }
}

__global__ __launch_bounds__(256) void softmax_kernel(float* __restrict__ attn)
{
    __shared__ float red[256];
    const int tid = threadIdx.x;
    float* row = attn + ((long long)blockIdx.y * FEAT + blockIdx.x) * FEAT;
    float v0 = row[tid];
    float v1 = (tid < FEAT - 256) ? row[tid + 256] : -1e30f;
    red[tid] = fmaxf(v0, v1);
    __syncthreads();
#pragma unroll
    for (int s = 128; s > 0; s >>= 1) {
        if (tid < s) red[tid] = fmaxf(red[tid], red[tid + s]);
        __syncthreads();
    }
    float m = red[0];
    __syncthreads();
    float e0 = expf(v0 - m);
    float e1 = (tid < FEAT - 256) ? expf(v1 - m) : 0.f;
    red[tid] = e0 + e1;
    __syncthreads();
#pragma unroll
    for (int s = 128; s > 0; s >>= 1) {
        if (tid < s) red[tid] += red[tid + s];
        __syncthreads();
    }
    float inv = 1.f / red[0];
    row[tid] = e0 * inv;
    if (tid < FEAT - 256) row[tid + 256] = e1 * inv;
}

__global__ __launch_bounds__(256) void ln_kernel(const float* __restrict__ tp,
                                                 const float* __restrict__ gamma,
                                                 const float* __restrict__ beta,
                                                 float* __restrict__ out)
{
    const int b = blockIdx.y;
    const int o = blockIdx.x * 256 + threadIdx.x;
    const float* base = tp + (long long)b * (FEAT * NPTS) + o;
    float s = 0.f, s2 = 0.f;
#pragma unroll 4
    for (int l = 0; l < FEAT; l++) {
        float v = base[(long long)l * NPTS];
        s += v;
        s2 += v * v;
    }
    const float inv = 1.f / FEAT;
    float mu = s * inv;
    float var = s2 * inv - mu * mu;
    float rstd = rsqrtf(var + 1e-5f);
    float* ob = out + (long long)b * (FEAT * NPTS) + o;
#pragma unroll 4
    for (int l = 0; l < FEAT; l++) {
        float v = base[(long long)l * NPTS];
        ob[(long long)l * NPTS] = (v - mu) * rstd * gamma[l] + beta[l];
    }
}

extern "C" void kernel_launch(void* const* d_in, const int* in_sizes, int n_in,
                              void* d_out, int out_size)
{
    const float* query   = (const float*)d_in[0];
    const float* support = (const float*)d_in[1];
    const float* Wq      = (const float*)d_in[2];
    const float* Wk      = (const float*)d_in[3];
    const float* Wv      = (const float*)d_in[4];
    const float* gamma   = (const float*)d_in[5];
    const float* beta    = (const float*)d_in[6];
    float* out = (float*)d_out;

    void* sp = nullptr;
    cudaGetSymbolAddress(&sp, g_scratch);
    float* S  = (float*)sp;
    float* qT = S + OFF_QT;
    float* kT = S + OFF_KT;
    float* vT = S + OFF_VT;
    float* at = S + OFF_AT;
    float* tp = S + OFF_TMP;

    const long long sX = (long long)FEAT * NPTS;   // 655360
    const long long sA = (long long)FEAT * FEAT;   // 102400
    dim3 blk(256);

    // qT[b,f,o] = sum_i support[b,f,i] * Wq[o,i]   (M=320,N=2048,K=2048)
    gemm_tf32_kernel<128, false><<<dim3(16, 5, NB), blk>>>(
        support, Wq, qT, nullptr, 2048, 2048, 2048, 2048, sX, 0, sX, 0, 1.f);
    // kT[b,f,o] = sum_i query[b,f,i] * Wk[o,i]
    gemm_tf32_kernel<128, false><<<dim3(16, 5, NB), blk>>>(
        query, Wk, kT, nullptr, 2048, 2048, 2048, 2048, sX, 0, sX, 0, 1.f);
    // vT[b,f,o] = sum_i query[b,f,i] * Wv[o,i]
    gemm_tf32_kernel<128, false><<<dim3(16, 5, NB), blk>>>(
        query, Wv, vT, nullptr, 2048, 2048, 2048, 2048, sX, 0, sX, 0, 1.f);
    // attn[b,l,m] = (1/sqrt(320)) * sum_o qT[b,l,o] * kT[b,m,o]   (M=320,N=320,K=2048)
    float alpha = 1.0f / sqrtf((float)FEAT);
    gemm_tf32_kernel<64, false><<<dim3(5, 5, NB), blk>>>(
        qT, kT, at, nullptr, 2048, 2048, 2048, 320, sX, sX, sA, 0, alpha);
    // row softmax over m
    softmax_kernel<<<dim3(FEAT, NB), blk>>>(at);
    // tmp[b,l,o] = sum_m attn[b,l,m] * vT[b,m,o] + query[b,l,o]   (M=320,N=2048,K=320, B row-major)
    gemm_tf32_kernel<128, true><<<dim3(16, 5, NB), blk>>>(
        at, vT, tp, query, 320, 320, 2048, 2048, sA, sX, sX, sX, 1.f);
    // LayerNorm over l (FEAT), write final output
    ln_kernel<<<dim3(NPTS / 256, NB), blk>>>(tp, gamma, beta, out);
}

// round 5
// speedup vs baseline: 1.6431x; 1.6431x over previous
#include <cuda_runtime.h>
#include <cstdint>
#include <cmath>

#define NB 32
#define FEAT 320
#define NPTS 2048

// scratch: qT(20971520) kT(20971520) vN(20971520) attn(3276800) tmp(20971520)
static __device__ float g_scratch[87162880];
#define OFF_QT 0LL
#define OFF_KT 20971520LL
#define OFF_VN 41943040LL
#define OFF_AT 62914560LL
#define OFF_TMP 66191360LL

// ---------------- PTX helpers ----------------
__device__ __forceinline__ uint32_t smem_u32(const void* p) {
    uint32_t a;
    asm("{ .reg .u64 t; cvta.to.shared.u64 t, %1; cvt.u32.u64 %0, t; }" : "=r"(a) : "l"(p));
    return a;
}

__device__ __forceinline__ void mma_tf32(float* d, const uint32_t* a, const uint32_t* b) {
    asm volatile(
        "mma.sync.aligned.m16n8k8.row.col.f32.tf32.tf32.f32 "
        "{%0,%1,%2,%3}, {%4,%5,%6,%7}, {%8,%9}, {%0,%1,%2,%3};"
        : "+f"(d[0]), "+f"(d[1]), "+f"(d[2]), "+f"(d[3])
        : "r"(a[0]), "r"(a[1]), "r"(a[2]), "r"(a[3]), "r"(b[0]), "r"(b[1]));
}

__device__ __forceinline__ void ldsm4(uint32_t* r, uint32_t addr) {
    asm volatile("ldmatrix.sync.aligned.m8n8.x4.shared.b16 {%0,%1,%2,%3}, [%4];"
                 : "=r"(r[0]), "=r"(r[1]), "=r"(r[2]), "=r"(r[3]) : "r"(addr));
}

__device__ __forceinline__ void cpasync16(uint32_t dst, const float* src, bool pred) {
    int sz = pred ? 16 : 0;
    asm volatile("cp.async.cg.shared.global [%0], [%1], 16, %2;"
                 :: "r"(dst), "l"(src), "r"(sz) : "memory");
}
#define CP_COMMIT() asm volatile("cp.async.commit_group;" ::: "memory")
#define CP_WAIT1()  asm volatile("cp.async.wait_group 1;" ::: "memory")

// ---------------- GEMM: C[M,N] = alpha*A[M,K]*B[N,K]^T (+D) ----------------
// BM=128, BN=256, BK=32, 3-stage cp.async pipeline, 256 threads (warps 2m x 4n),
// warp tile 64x64 via mma.sync.m16n8k8.tf32. TRANSC: C stored as C[n][m-flat]
// with batch decoded from the flat m index (for vN).
#define STAGE_BYTES 49152         // A 16KB + B 32KB
#define SMEM_TOTAL_BYTES (3 * STAGE_BYTES)

template<bool TRANSC>
__global__ __launch_bounds__(256, 1)
void gemm_mma_kernel(const float* __restrict__ Ag, const float* __restrict__ Bg,
                     float* __restrict__ Cg, const float* __restrict__ Dg,
                     int M, int N, int K, int lda, int ldb, int ldc,
                     long long sA, long long sB, long long sC, long long sD,
                     float alpha)
{
    extern __shared__ char smem[];
    const uint32_t sb = smem_u32(smem);

    const int tid  = threadIdx.x;
    const int lane = tid & 31;
    const int warp = tid >> 5;
    const int wm = warp & 1;
    const int wn = warp >> 1;
    const int bm = blockIdx.y * 128;
    const int bn = blockIdx.x * 256;
    const int b  = blockIdx.z;

    const float* Ab = Ag + (long long)b * sA;
    const float* Bb = Bg + (long long)b * sB;

    // per-thread load constants
    const int r0  = tid >> 3;
    const int seg = tid & 7;
    const uint32_t xorterm = (uint32_t)((seg ^ (r0 & 7)) << 4);

    // ldmatrix address constants
    const int rA_loc = lane & 15;
    const int hiA    = lane >> 4;
    const int rB_loc = (lane & 7) | ((lane >> 4) << 3);
    const int hiB    = (lane >> 3) & 1;
    uint32_t offA[4], phA[4], offB[4], phB[4];
#pragma unroll
    for (int mt = 0; mt < 4; mt++) {
        int rowA = wm * 64 + mt * 16 + rA_loc;
        offA[mt] = (uint32_t)(rowA * 128);
        phA[mt]  = (uint32_t)(rowA & 7);
    }
#pragma unroll
    for (int np = 0; np < 4; np++) {
        int rowB = wn * 64 + np * 16 + rB_loc;
        offB[np] = (uint32_t)(rowB * 128);
        phB[np]  = (uint32_t)(rowB & 7);
    }

    float acc[4][8][4];
#pragma unroll
    for (int i = 0; i < 4; i++)
#pragma unroll
        for (int j = 0; j < 8; j++)
#pragma unroll
            for (int r = 0; r < 4; r++) acc[i][j][r] = 0.f;

    const int NC = K >> 5;

    auto ISSUE = [&](int c) {
        const int k0 = c << 5;
        const uint32_t aB = sb + (uint32_t)((c % 3) * STAGE_BYTES);
        const uint32_t bB = aB + 16384;
#pragma unroll
        for (int i = 0; i < 4; i++) {
            int r = r0 + 32 * i;
            int gr = bm + r;
            bool p = gr < M;
            const float* src = Ab + (long long)(p ? gr : 0) * lda + k0 + seg * 4;
            cpasync16(aB + (uint32_t)(r * 128) + xorterm, src, p);
        }
#pragma unroll
        for (int i = 0; i < 8; i++) {
            int r = r0 + 32 * i;
            int gn = bn + r;
            bool p = gn < N;
            const float* src = Bb + (long long)(p ? gn : 0) * ldb + k0 + seg * 4;
            cpasync16(bB + (uint32_t)(r * 128) + xorterm, src, p);
        }
        CP_COMMIT();
    };

    ISSUE(0);
    ISSUE(1);

    for (int c = 0; c < NC; c++) {
        CP_WAIT1();
        __syncthreads();
        if (c + 2 < NC) ISSUE(c + 2);
        else CP_COMMIT();

        const uint32_t aB = sb + (uint32_t)((c % 3) * STAGE_BYTES);
        const uint32_t bB = aB + 16384;
#pragma unroll
        for (int ks = 0; ks < 4; ks++) {
            uint32_t a[4][4];
            uint32_t bf[8][2];
#pragma unroll
            for (int mt = 0; mt < 4; mt++) {
                uint32_t sA_ = (uint32_t)(2 * ks + hiA);
                ldsm4(a[mt], aB + offA[mt] + (((sA_ ^ phA[mt])) << 4));
            }
#pragma unroll
            for (int np = 0; np < 4; np++) {
                uint32_t r[4];
                uint32_t sB_ = (uint32_t)(2 * ks + hiB);
                ldsm4(r, bB + offB[np] + (((sB_ ^ phB[np])) << 4));
                bf[2 * np][0] = r[0]; bf[2 * np][1] = r[1];
                bf[2 * np + 1][0] = r[2]; bf[2 * np + 1][1] = r[3];
            }
#pragma unroll
            for (int mt = 0; mt < 4; mt++)
#pragma unroll
                for (int nt = 0; nt < 8; nt++)
                    mma_tf32(acc[mt][nt], a[mt], bf[nt]);
        }
    }

    if (!TRANSC) {
        float* Cb = Cg + (long long)b * sC;
        const float* Db = Dg ? (Dg + (long long)b * sD) : nullptr;
#pragma unroll
        for (int mt = 0; mt < 4; mt++) {
#pragma unroll
            for (int nt = 0; nt < 8; nt++) {
                int row = bm + wm * 64 + mt * 16 + (lane >> 2);
                int col = bn + wn * 64 + nt * 8 + ((lane & 3) << 1);
                if (col < N) {
                    if (row < M) {
                        long long i0 = (long long)row * ldc + col;
                        float2 v;
                        v.x = alpha * acc[mt][nt][0];
                        v.y = alpha * acc[mt][nt][1];
                        if (Db) { v.x += Db[i0]; v.y += Db[i0 + 1]; }
                        *reinterpret_cast<float2*>(Cb + i0) = v;
                    }
                    if (row + 8 < M) {
                        long long i1 = (long long)(row + 8) * ldc + col;
                        float2 v;
                        v.x = alpha * acc[mt][nt][2];
                        v.y = alpha * acc[mt][nt][3];
                        if (Db) { v.x += Db[i1]; v.y += Db[i1 + 1]; }
                        *reinterpret_cast<float2*>(Cb + i1) = v;
                    }
                }
            }
        }
    } else {
        // transposed store via smem staging: Cs[128 n][132 m] per half
        float* Cs = reinterpret_cast<float*>(smem);
        __syncthreads();
#pragma unroll
        for (int p = 0; p < 2; p++) {
            if ((wn >> 1) == p) {
#pragma unroll
                for (int mt = 0; mt < 4; mt++) {
#pragma unroll
                    for (int nt = 0; nt < 8; nt++) {
                        int nl = wn * 64 + nt * 8 + ((lane & 3) << 1) - p * 128;
                        int m0 = wm * 64 + mt * 16 + (lane >> 2);
                        Cs[nl * 132 + m0]           = alpha * acc[mt][nt][0];
                        Cs[(nl + 1) * 132 + m0]     = alpha * acc[mt][nt][1];
                        Cs[nl * 132 + m0 + 8]       = alpha * acc[mt][nt][2];
                        Cs[(nl + 1) * 132 + m0 + 8] = alpha * acc[mt][nt][3];
                    }
                }
            }
            __syncthreads();
#pragma unroll
            for (int it = 0; it < 16; it++) {
                int linear = tid + it * 256;
                int row = linear >> 5;        // 0..127  (n local)
                int c4  = linear & 31;        // float4 index along m
                int n_g = bn + p * 128 + row; // always < N (N=2048 here)
                int m_g = bm + c4 * 4;        // flat m, always < M
                int bb  = m_g / FEAT;
                int mm  = m_g - bb * FEAT;
                float4 v = *reinterpret_cast<const float4*>(&Cs[row * 132 + c4 * 4]);
                *reinterpret_cast<float4*>(Cg + (long long)bb * sC + (long long)n_g * ldc + mm) = v;
            }
            __syncthreads();
        }
    }
}

// ---------------- softmax / layernorm ----------------
__global__ __launch_bounds__(256) void softmax_kernel(float* __restrict__ attn)
{
    __shared__ float red[256];
    const int tid = threadIdx.x;
    float* row = attn + ((long long)blockIdx.y * FEAT + blockIdx.x) * FEAT;
    float v0 = row[tid];
    float v1 = (tid < FEAT - 256) ? row[tid + 256] : -1e30f;
    red[tid] = fmaxf(v0, v1);
    __syncthreads();
#pragma unroll
    for (int s = 128; s > 0; s >>= 1) {
        if (tid < s) red[tid] = fmaxf(red[tid], red[tid + s]);
        __syncthreads();
    }
    float m = red[0];
    __syncthreads();
    float e0 = expf(v0 - m);
    float e1 = (tid < FEAT - 256) ? expf(v1 - m) : 0.f;
    red[tid] = e0 + e1;
    __syncthreads();
#pragma unroll
    for (int s = 128; s > 0; s >>= 1) {
        if (tid < s) red[tid] += red[tid + s];
        __syncthreads();
    }
    float inv = 1.f / red[0];
    row[tid] = e0 * inv;
    if (tid < FEAT - 256) row[tid + 256] = e1 * inv;
}

__global__ __launch_bounds__(256) void ln_kernel(const float* __restrict__ tp,
                                                 const float* __restrict__ gamma,
                                                 const float* __restrict__ beta,
                                                 float* __restrict__ out)
{
    const int b = blockIdx.y;
    const int o = blockIdx.x * 256 + threadIdx.x;
    const float* base = tp + (long long)b * (FEAT * NPTS) + o;
    float s = 0.f, s2 = 0.f;
#pragma unroll 4
    for (int l = 0; l < FEAT; l++) {
        float v = base[(long long)l * NPTS];
        s += v;
        s2 += v * v;
    }
    const float inv = 1.f / FEAT;
    float mu = s * inv;
    float var = s2 * inv - mu * mu;
    float rstd = rsqrtf(var + 1e-5f);
    float* ob = out + (long long)b * (FEAT * NPTS) + o;
#pragma unroll 4
    for (int l = 0; l < FEAT; l++) {
        float v = base[(long long)l * NPTS];
        ob[(long long)l * NPTS] = (v - mu) * rstd * gamma[l] + beta[l];
    }
}

// ---------------- launch ----------------
extern "C" void kernel_launch(void* const* d_in, const int* in_sizes, int n_in,
                              void* d_out, int out_size)
{
    const float* query   = (const float*)d_in[0];
    const float* support = (const float*)d_in[1];
    const float* Wq      = (const float*)d_in[2];
    const float* Wk      = (const float*)d_in[3];
    const float* Wv      = (const float*)d_in[4];
    const float* gamma   = (const float*)d_in[5];
    const float* beta    = (const float*)d_in[6];
    float* out = (float*)d_out;

    void* sp = nullptr;
    cudaGetSymbolAddress(&sp, g_scratch);
    float* S  = (float*)sp;
    float* qT = S + OFF_QT;
    float* kT = S + OFF_KT;
    float* vN = S + OFF_VN;
    float* at = S + OFF_AT;
    float* tp = S + OFF_TMP;

    const long long sX  = (long long)FEAT * NPTS;   // 655360
    const long long sAt = (long long)FEAT * FEAT;   // 102400
    const int MF = NB * FEAT;                       // 10240 flattened M

    static bool attr_set = false;
    if (!attr_set) {
        cudaFuncSetAttribute(gemm_mma_kernel<false>,
                             cudaFuncAttributeMaxDynamicSharedMemorySize, SMEM_TOTAL_BYTES);
        cudaFuncSetAttribute(gemm_mma_kernel<true>,
                             cudaFuncAttributeMaxDynamicSharedMemorySize, SMEM_TOTAL_BYTES);
        attr_set = true;
    }

    dim3 blk(256);
    const size_t smb = SMEM_TOTAL_BYTES;
    const float alpha = 1.0f / sqrtf((float)FEAT);

    // QKV as flattened 10240 x 2048 x 2048 GEMMs (X contiguous as [(b,f), i])
    // qT[(b,f)][o] = sum_i support[(b,f)][i] * Wq[o][i]
    gemm_mma_kernel<false><<<dim3(8, 80, 1), blk, smb>>>(
        support, Wq, qT, nullptr, MF, 2048, 2048, 2048, 2048, 2048, 0, 0, 0, 0, 1.f);
    // kT[(b,f)][o] = sum_i query[(b,f)][i] * Wk[o][i]
    gemm_mma_kernel<false><<<dim3(8, 80, 1), blk, smb>>>(
        query, Wk, kT, nullptr, MF, 2048, 2048, 2048, 2048, 2048, 0, 0, 0, 0, 1.f);
    // vN[b][o][m] = sum_i query[(b,m)][i] * Wv[o][i]  (transposed store, ldc=320, sC=655360)
    gemm_mma_kernel<true><<<dim3(8, 80, 1), blk, smb>>>(
        query, Wv, vN, nullptr, MF, 2048, 2048, 2048, 2048, 320, 0, 0, sX, 0, 1.f);
    // attn[b][l][m] = alpha * sum_o qT[b,l][o] * kT[b,m][o]   M=320,N=320,K=2048
    gemm_mma_kernel<false><<<dim3(2, 3, NB), blk, smb>>>(
        qT, kT, at, nullptr, 320, 320, 2048, 2048, 2048, 320, sX, sX, sAt, 0, alpha);
    // row softmax over m
    softmax_kernel<<<dim3(FEAT, NB), blk>>>(at);
    // tmp[b][l][o] = sum_m attn[b][l][m] * vN[b][o][m] + query[b][l][o]  M=320,N=2048,K=320
    gemm_mma_kernel<false><<<dim3(8, 3, NB), blk, smb>>>(
        at, vN, tp, query, 320, 2048, 320, 320, 320, 2048, sAt, sX, sX, sX, 1.f);
    // LayerNorm over l (FEAT)
    ln_kernel<<<dim3(NPTS / 256, NB), blk>>>(tp, gamma, beta, out);
}

// round 6
// speedup vs baseline: 2.0887x; 1.2712x over previous
#include <cuda_runtime.h>
#include <cstdint>
#include <cmath>

#define NB 32
#define FEAT 320
#define NPTS 2048

// scratch: qT(20971520) kT(20971520) vN(20971520) attn(3276800) tmp(20971520)
static __device__ float g_scratch[87162880];
#define OFF_QT 0LL
#define OFF_KT 20971520LL
#define OFF_VN 41943040LL
#define OFF_AT 62914560LL
#define OFF_TMP 66191360LL

#define STAGE_BYTES 32768          // A 16KB + B 16KB
#define SMEM_TOTAL_BYTES (3 * STAGE_BYTES)

// ---------------- PTX helpers ----------------
__device__ __forceinline__ uint32_t smem_u32(const void* p) {
    uint32_t a;
    asm("{ .reg .u64 t; cvta.to.shared.u64 t, %1; cvt.u32.u64 %0, t; }" : "=r"(a) : "l"(p));
    return a;
}

__device__ __forceinline__ void mma_tf32(float* d, const uint32_t* a, const uint32_t* b) {
    asm volatile(
        "mma.sync.aligned.m16n8k8.row.col.f32.tf32.tf32.f32 "
        "{%0,%1,%2,%3}, {%4,%5,%6,%7}, {%8,%9}, {%0,%1,%2,%3};"
        : "+f"(d[0]), "+f"(d[1]), "+f"(d[2]), "+f"(d[3])
        : "r"(a[0]), "r"(a[1]), "r"(a[2]), "r"(a[3]), "r"(b[0]), "r"(b[1]));
}

__device__ __forceinline__ void ldsm4(uint32_t* r, uint32_t addr) {
    asm volatile("ldmatrix.sync.aligned.m8n8.x4.shared.b16 {%0,%1,%2,%3}, [%4];"
                 : "=r"(r[0]), "=r"(r[1]), "=r"(r[2]), "=r"(r[3]) : "r"(addr));
}

__device__ __forceinline__ void cpasync16(uint32_t dst, const float* src, bool pred) {
    int sz = pred ? 16 : 0;
    asm volatile("cp.async.cg.shared.global [%0], [%1], 16, %2;"
                 :: "r"(dst), "l"(src), "r"(sz) : "memory");
}
#define CP_COMMIT() asm volatile("cp.async.commit_group;" ::: "memory")
#define CP_WAIT1()  asm volatile("cp.async.wait_group 1;" ::: "memory")

// ---------------- tile core ----------------
// One 128x128 output tile of C[M,N] = alpha*A[M,K]*B[N,K]^T (+D).
// 128 threads, warps 2m x 2n, warp tile 64x64, BK=32, 3-stage cp.async.
// TRANSC: scatter C transposed as C[batch][n][m%FEAT] via smem staging
// (batch decoded from flat m; used for vN).
template<bool TRANSC>
__device__ __forceinline__ void run_tile(
    const float* __restrict__ A, const float* __restrict__ B,
    float* __restrict__ C, const float* __restrict__ D,
    int M, int N, int K, int lda, int ldb, int ldc, long long sCb,
    int bm, int bn, float alpha, uint32_t sb, char* smem)
{
    const int tid  = threadIdx.x;
    const int lane = tid & 31;
    const int warp = tid >> 5;
    const int wm = warp & 1;
    const int wn = warp >> 1;

    const int r0  = tid >> 3;          // 0..15
    const int seg = tid & 7;
    const uint32_t xorterm = (uint32_t)((seg ^ (r0 & 7)) << 4);

    const int rA_loc = lane & 15;
    const int hiA    = lane >> 4;
    const int rB_loc = (lane & 7) | ((lane >> 4) << 3);
    const int hiB    = (lane >> 3) & 1;
    uint32_t offA[4], phA[4], offB[4], phB[4];
#pragma unroll
    for (int mt = 0; mt < 4; mt++) {
        int rowA = wm * 64 + mt * 16 + rA_loc;
        offA[mt] = (uint32_t)(rowA * 128);
        phA[mt]  = (uint32_t)(rowA & 7);
    }
#pragma unroll
    for (int np = 0; np < 4; np++) {
        int rowB = wn * 64 + np * 16 + rB_loc;
        offB[np] = (uint32_t)(rowB * 128);
        phB[np]  = (uint32_t)(rowB & 7);
    }

    float acc[4][8][4];
#pragma unroll
    for (int i = 0; i < 4; i++)
#pragma unroll
        for (int j = 0; j < 8; j++)
#pragma unroll
            for (int r = 0; r < 4; r++) acc[i][j][r] = 0.f;

    const int NC = K >> 5;

    auto ISSUE = [&](int c) {
        const int k0 = c << 5;
        const uint32_t aB = sb + (uint32_t)((c % 3) * STAGE_BYTES);
        const uint32_t bB = aB + 16384;
#pragma unroll
        for (int i = 0; i < 8; i++) {
            int r = r0 + 16 * i;
            int gr = bm + r;
            bool p = gr < M;
            cpasync16(aB + (uint32_t)(r * 128) + xorterm,
                      A + (long long)(p ? gr : 0) * lda + k0 + seg * 4, p);
        }
#pragma unroll
        for (int i = 0; i < 8; i++) {
            int r = r0 + 16 * i;
            int gn = bn + r;
            bool p = gn < N;
            cpasync16(bB + (uint32_t)(r * 128) + xorterm,
                      B + (long long)(p ? gn : 0) * ldb + k0 + seg * 4, p);
        }
        CP_COMMIT();
    };

    ISSUE(0);
    ISSUE(1);

    for (int c = 0; c < NC; c++) {
        CP_WAIT1();
        __syncthreads();
        if (c + 2 < NC) ISSUE(c + 2);
        else CP_COMMIT();

        const uint32_t aB = sb + (uint32_t)((c % 3) * STAGE_BYTES);
        const uint32_t bB = aB + 16384;
#pragma unroll
        for (int ks = 0; ks < 4; ks++) {
            uint32_t a[4][4];
            uint32_t bf[8][2];
#pragma unroll
            for (int mt = 0; mt < 4; mt++) {
                uint32_t sA_ = (uint32_t)(2 * ks + hiA);
                ldsm4(a[mt], aB + offA[mt] + ((sA_ ^ phA[mt]) << 4));
            }
#pragma unroll
            for (int np = 0; np < 4; np++) {
                uint32_t r[4];
                uint32_t sB_ = (uint32_t)(2 * ks + hiB);
                ldsm4(r, bB + offB[np] + ((sB_ ^ phB[np]) << 4));
                bf[2 * np][0] = r[0]; bf[2 * np][1] = r[1];
                bf[2 * np + 1][0] = r[2]; bf[2 * np + 1][1] = r[3];
            }
#pragma unroll
            for (int mt = 0; mt < 4; mt++)
#pragma unroll
                for (int nt = 0; nt < 8; nt++)
                    mma_tf32(acc[mt][nt], a[mt], bf[nt]);
        }
    }

    if (!TRANSC) {
#pragma unroll
        for (int mt = 0; mt < 4; mt++) {
#pragma unroll
            for (int nt = 0; nt < 8; nt++) {
                int row = bm + wm * 64 + mt * 16 + (lane >> 2);
                int col = bn + wn * 64 + nt * 8 + ((lane & 3) << 1);
                if (col < N) {
                    if (row < M) {
                        long long i0 = (long long)row * ldc + col;
                        float2 v;
                        v.x = alpha * acc[mt][nt][0];
                        v.y = alpha * acc[mt][nt][1];
                        if (D) { v.x += D[i0]; v.y += D[i0 + 1]; }
                        *reinterpret_cast<float2*>(C + i0) = v;
                    }
                    if (row + 8 < M) {
                        long long i1 = (long long)(row + 8) * ldc + col;
                        float2 v;
                        v.x = alpha * acc[mt][nt][2];
                        v.y = alpha * acc[mt][nt][3];
                        if (D) { v.x += D[i1]; v.y += D[i1 + 1]; }
                        *reinterpret_cast<float2*>(C + i1) = v;
                    }
                }
            }
        }
    } else {
        // stage 128n x 132m floats in smem, then coalesced scatter
        float* Cs = reinterpret_cast<float*>(smem);
        __syncthreads();   // all warps done reading stage smem
#pragma unroll
        for (int mt = 0; mt < 4; mt++) {
#pragma unroll
            for (int nt = 0; nt < 8; nt++) {
                int nl = wn * 64 + nt * 8 + ((lane & 3) << 1);
                int m0 = wm * 64 + mt * 16 + (lane >> 2);
                Cs[nl * 132 + m0]           = alpha * acc[mt][nt][0];
                Cs[(nl + 1) * 132 + m0]     = alpha * acc[mt][nt][1];
                Cs[nl * 132 + m0 + 8]       = alpha * acc[mt][nt][2];
                Cs[(nl + 1) * 132 + m0 + 8] = alpha * acc[mt][nt][3];
            }
        }
        __syncthreads();
#pragma unroll
        for (int it = 0; it < 32; it++) {
            int linear = tid + it * 128;
            int row = linear >> 5;          // 0..127 local n
            int c4  = linear & 31;          // float4 idx along m
            int n_g = bn + row;             // < N (2048)
            int m_g = bm + c4 * 4;          // flat m
            int bb  = m_g / FEAT;
            int mm  = m_g - bb * FEAT;
            float4 v = *reinterpret_cast<const float4*>(&Cs[row * 132 + c4 * 4]);
            *reinterpret_cast<float4*>(C + (long long)bb * sCb + (long long)n_g * ldc + mm) = v;
        }
    }
}

// ---------------- fused persistent QKV ----------------
#define QKV_TILES_PER_OP 1280     // 80 bm x 16 bn
#define QKV_NTILES 3840

__global__ __launch_bounds__(128, 2)
void qkv_kernel(const float* __restrict__ query, const float* __restrict__ support,
                const float* __restrict__ Wq, const float* __restrict__ Wk,
                const float* __restrict__ Wv,
                float* __restrict__ qT, float* __restrict__ kT, float* __restrict__ vN)
{
    extern __shared__ char smem[];
    const uint32_t sb = smem_u32(smem);
    const long long sX = (long long)FEAT * NPTS;

    for (int t = blockIdx.x; t < QKV_NTILES; t += gridDim.x) {
        int op = t / QKV_TILES_PER_OP;
        int r  = t - op * QKV_TILES_PER_OP;
        int bm = (r >> 4) * 128;
        int bn = (r & 15) * 128;
        __syncthreads();   // protect smem reuse across tiles
        if (op == 0) {
            run_tile<false>(support, Wq, qT, nullptr,
                            NB * FEAT, 2048, 2048, 2048, 2048, 2048, 0,
                            bm, bn, 1.f, sb, smem);
        } else if (op == 1) {
            run_tile<false>(query, Wk, kT, nullptr,
                            NB * FEAT, 2048, 2048, 2048, 2048, 2048, 0,
                            bm, bn, 1.f, sb, smem);
        } else {
            run_tile<true>(query, Wv, vN, nullptr,
                           NB * FEAT, 2048, 2048, 2048, 2048, 320, sX,
                           bm, bn, 1.f, sb, smem);
        }
    }
}

// ---------------- generic persistent batched GEMM ----------------
__global__ __launch_bounds__(128, 2)
void gemm128_kernel(const float* __restrict__ Ag, const float* __restrict__ Bg,
                    float* __restrict__ Cg, const float* __restrict__ Dg,
                    int M, int N, int K, int lda, int ldb, int ldc,
                    long long sA, long long sB, long long sC, long long sD,
                    float alpha, int ntiles, int tn)
{
    extern __shared__ char smem[];
    const uint32_t sb = smem_u32(smem);
    const int per = ((M + 127) >> 7) * tn;

    for (int t = blockIdx.x; t < ntiles; t += gridDim.x) {
        int b = t / per;
        int r = t - b * per;
        int bm = (r / tn) * 128;
        int bn = (r % tn) * 128;
        __syncthreads();
        run_tile<false>(Ag + (long long)b * sA, Bg + (long long)b * sB,
                        Cg + (long long)b * sC,
                        Dg ? (Dg + (long long)b * sD) : nullptr,
                        M, N, K, lda, ldb, ldc, 0, bm, bn, alpha, sb, smem);
    }
}

// ---------------- softmax / layernorm ----------------
__global__ __launch_bounds__(256) void softmax_kernel(float* __restrict__ attn)
{
    __shared__ float red[256];
    const int tid = threadIdx.x;
    float* row = attn + ((long long)blockIdx.y * FEAT + blockIdx.x) * FEAT;
    float v0 = row[tid];
    float v1 = (tid < FEAT - 256) ? row[tid + 256] : -1e30f;
    red[tid] = fmaxf(v0, v1);
    __syncthreads();
#pragma unroll
    for (int s = 128; s > 0; s >>= 1) {
        if (tid < s) red[tid] = fmaxf(red[tid], red[tid + s]);
        __syncthreads();
    }
    float m = red[0];
    __syncthreads();
    float e0 = expf(v0 - m);
    float e1 = (tid < FEAT - 256) ? expf(v1 - m) : 0.f;
    red[tid] = e0 + e1;
    __syncthreads();
#pragma unroll
    for (int s = 128; s > 0; s >>= 1) {
        if (tid < s) red[tid] += red[tid + s];
        __syncthreads();
    }
    float inv = 1.f / red[0];
    row[tid] = e0 * inv;
    if (tid < FEAT - 256) row[tid + 256] = e1 * inv;
}

__global__ __launch_bounds__(256) void ln_kernel(const float* __restrict__ tp,
                                                 const float* __restrict__ gamma,
                                                 const float* __restrict__ beta,
                                                 float* __restrict__ out)
{
    const int b = blockIdx.y;
    const int o = blockIdx.x * 256 + threadIdx.x;
    const float* base = tp + (long long)b * (FEAT * NPTS) + o;
    float s = 0.f, s2 = 0.f;
#pragma unroll 4
    for (int l = 0; l < FEAT; l++) {
        float v = base[(long long)l * NPTS];
        s += v;
        s2 += v * v;
    }
    const float inv = 1.f / FEAT;
    float mu = s * inv;
    float var = s2 * inv - mu * mu;
    float rstd = rsqrtf(var + 1e-5f);
    float* ob = out + (long long)b * (FEAT * NPTS) + o;
#pragma unroll 4
    for (int l = 0; l < FEAT; l++) {
        float v = base[(long long)l * NPTS];
        ob[(long long)l * NPTS] = (v - mu) * rstd * gamma[l] + beta[l];
    }
}

// ---------------- launch ----------------
extern "C" void kernel_launch(void* const* d_in, const int* in_sizes, int n_in,
                              void* d_out, int out_size)
{
    const float* query   = (const float*)d_in[0];
    const float* support = (const float*)d_in[1];
    const float* Wq      = (const float*)d_in[2];
    const float* Wk      = (const float*)d_in[3];
    const float* Wv      = (const float*)d_in[4];
    const float* gamma   = (const float*)d_in[5];
    const float* beta    = (const float*)d_in[6];
    float* out = (float*)d_out;

    void* sp = nullptr;
    cudaGetSymbolAddress(&sp, g_scratch);
    float* S  = (float*)sp;
    float* qT = S + OFF_QT;
    float* kT = S + OFF_KT;
    float* vN = S + OFF_VN;
    float* at = S + OFF_AT;
    float* tp = S + OFF_TMP;

    const long long sX  = (long long)FEAT * NPTS;   // 655360
    const long long sAt = (long long)FEAT * FEAT;   // 102400

    static bool attr_set = false;
    if (!attr_set) {
        cudaFuncSetAttribute(qkv_kernel,
                             cudaFuncAttributeMaxDynamicSharedMemorySize, SMEM_TOTAL_BYTES);
        cudaFuncSetAttribute(gemm128_kernel,
                             cudaFuncAttributeMaxDynamicSharedMemorySize, SMEM_TOTAL_BYTES);
        attr_set = true;
    }

    const size_t smb = SMEM_TOTAL_BYTES;
    const float alpha = 1.0f / sqrtf((float)FEAT);

    // fused persistent QKV: qT, kT (flat 10240x2048) + vN (transposed scatter)
    qkv_kernel<<<296, 128, smb>>>(query, support, Wq, Wk, Wv, qT, kT, vN);
    // attn[b][l][m] = alpha * qT[b,l,:] . kT[b,m,:]   M=320,N=320,K=2048 (tn=3, 288 tiles)
    gemm128_kernel<<<288, 128, smb>>>(
        qT, kT, at, nullptr, 320, 320, 2048, 2048, 2048, 320,
        sX, sX, sAt, 0, alpha, 288, 3);
    // row softmax over m
    softmax_kernel<<<dim3(FEAT, NB), 256>>>(at);
    // tmp[b][l][o] = attn[b,l,:] . vN[b,o,:] + query[b,l,o]  M=320,N=2048,K=320 (tn=16, 1536 tiles)
    gemm128_kernel<<<296, 128, smb>>>(
        at, vN, tp, query, 320, 2048, 320, 320, 320, 2048,
        sAt, sX, sX, sX, 1.f, 1536, 16);
    // LayerNorm over l (FEAT)
    ln_kernel<<<dim3(NPTS / 256, NB), 256>>>(tp, gamma, beta, out);
}

// round 7
// speedup vs baseline: 2.1639x; 1.0360x over previous
#include <cuda_runtime.h>
#include <cuda_fp16.h>
#include <cstdint>
#include <cmath>

#define NB 32
#define FEAT 320
#define NPTS 2048

static __device__ float g_scratch[87162880];   // 348 MB

// byte offsets into scratch
#define O_SUPH 0LL
#define O_QRYH 41943040LL
#define O_WQH  83886080LL
#define O_WKH  92274688LL
#define O_WVH  100663296LL
#define O_QTH  109051904LL
#define O_KTH  150994944LL
#define O_VNH  192937984LL
#define O_ATF  234881024LL
#define O_PRH  247988224LL
#define O_TMPF 254541824LL

#define STAGE_BYTES 32768          // A 16KB + B 16KB (fp16, BK=64)
#define SMEM_TOTAL_BYTES (3 * STAGE_BYTES)

#define OM_HALF   0
#define OM_TRANS  1
#define OM_F32A   2
#define OM_F32RES 3

// ---------------- PTX helpers ----------------
__device__ __forceinline__ uint32_t smem_u32(const void* p) {
    uint32_t a;
    asm("{ .reg .u64 t; cvta.to.shared.u64 t, %1; cvt.u32.u64 %0, t; }" : "=r"(a) : "l"(p));
    return a;
}

__device__ __forceinline__ void mma_f16(float* d, const uint32_t* a, const uint32_t* b) {
    asm volatile(
        "mma.sync.aligned.m16n8k16.row.col.f32.f16.f16.f32 "
        "{%0,%1,%2,%3}, {%4,%5,%6,%7}, {%8,%9}, {%0,%1,%2,%3};"
        : "+f"(d[0]), "+f"(d[1]), "+f"(d[2]), "+f"(d[3])
        : "r"(a[0]), "r"(a[1]), "r"(a[2]), "r"(a[3]), "r"(b[0]), "r"(b[1]));
}

__device__ __forceinline__ void ldsm4(uint32_t* r, uint32_t addr) {
    asm volatile("ldmatrix.sync.aligned.m8n8.x4.shared.b16 {%0,%1,%2,%3}, [%4];"
                 : "=r"(r[0]), "=r"(r[1]), "=r"(r[2]), "=r"(r[3]) : "r"(addr));
}

__device__ __forceinline__ void cpasync16(uint32_t dst, const void* src, bool pred) {
    int sz = pred ? 16 : 0;
    asm volatile("cp.async.cg.shared.global [%0], [%1], 16, %2;"
                 :: "r"(dst), "l"(src), "r"(sz) : "memory");
}
#define CP_COMMIT() asm volatile("cp.async.commit_group;" ::: "memory")
#define CP_WAIT1()  asm volatile("cp.async.wait_group 1;" ::: "memory")

// ---------------- fp16 tile core ----------------
// One 128x128 tile of C = alpha*A[M,K]*B[N,K]^T (+D). A,B fp16 K-contiguous.
// BK=64 (one 128B smem row per tile row), 3-stage cp.async, 128 threads,
// warps 2x2, warp tile 64x64, mma m16n8k16.
template<int OM>
__device__ __forceinline__ void run_tile_h(
    const __half* __restrict__ A, const __half* __restrict__ B,
    char* __restrict__ Cb, const float* __restrict__ D,
    int M, int N, int K, int lda, int ldb, int ldc, long long sCb,
    int bm, int bn, float alpha, uint32_t sb, char* smem)
{
    const int tid  = threadIdx.x;
    const int lane = tid & 31;
    const int warp = tid >> 5;
    const int wm = warp & 1;
    const int wn = warp >> 1;

    const int r0  = tid >> 3;          // 0..15
    const int seg = tid & 7;
    const uint32_t xorterm = (uint32_t)((seg ^ (r0 & 7)) << 4);

    // ldmatrix lane->address decomposition
    const int mrowA = ((lane >> 3) & 1) * 8 + (lane & 7);
    const int khA   = lane >> 4;              // 0/1
    const int nrowB = (lane >> 4) * 8 + (lane & 7);
    const int khB   = (lane >> 3) & 1;
    uint32_t offA[4], phA[4], offB[4], phB[4];
#pragma unroll
    for (int mt = 0; mt < 4; mt++) {
        int rowA = wm * 64 + mt * 16 + mrowA;
        offA[mt] = (uint32_t)(rowA * 128);
        phA[mt]  = (uint32_t)(rowA & 7);
    }
#pragma unroll
    for (int np = 0; np < 4; np++) {
        int rowB = wn * 64 + np * 16 + nrowB;
        offB[np] = (uint32_t)(rowB * 128);
        phB[np]  = (uint32_t)(rowB & 7);
    }

    float acc[4][8][4];
#pragma unroll
    for (int i = 0; i < 4; i++)
#pragma unroll
        for (int j = 0; j < 8; j++)
#pragma unroll
            for (int r = 0; r < 4; r++) acc[i][j][r] = 0.f;

    const int NC = K >> 6;   // BK=64

    auto ISSUE = [&](int c) {
        const int k0 = c << 6;
        const uint32_t aB = sb + (uint32_t)((c % 3) * STAGE_BYTES);
        const uint32_t bB = aB + 16384;
#pragma unroll
        for (int i = 0; i < 8; i++) {
            int r = r0 + 16 * i;
            int gr = bm + r;
            bool p = gr < M;
            cpasync16(aB + (uint32_t)(r * 128) + xorterm,
                      A + (long long)(p ? gr : 0) * lda + k0 + seg * 8, p);
        }
#pragma unroll
        for (int i = 0; i < 8; i++) {
            int r = r0 + 16 * i;
            int gn = bn + r;
            bool p = gn < N;
            cpasync16(bB + (uint32_t)(r * 128) + xorterm,
                      B + (long long)(p ? gn : 0) * ldb + k0 + seg * 8, p);
        }
        CP_COMMIT();
    };

    ISSUE(0);
    ISSUE(1);

    for (int c = 0; c < NC; c++) {
        CP_WAIT1();
        __syncthreads();
        if (c + 2 < NC) ISSUE(c + 2);
        else CP_COMMIT();

        const uint32_t aB = sb + (uint32_t)((c % 3) * STAGE_BYTES);
        const uint32_t bB = aB + 16384;
#pragma unroll
        for (int ks = 0; ks < 4; ks++) {   // 4 k16 steps
            uint32_t a[4][4];
            uint32_t bf[8][2];
#pragma unroll
            for (int mt = 0; mt < 4; mt++) {
                uint32_t s16 = (uint32_t)(2 * ks + khA);
                ldsm4(a[mt], aB + offA[mt] + ((s16 ^ phA[mt]) << 4));
            }
#pragma unroll
            for (int np = 0; np < 4; np++) {
                uint32_t r[4];
                uint32_t s16 = (uint32_t)(2 * ks + khB);
                ldsm4(r, bB + offB[np] + ((s16 ^ phB[np]) << 4));
                bf[2 * np][0] = r[0];     bf[2 * np][1] = r[1];
                bf[2 * np + 1][0] = r[2]; bf[2 * np + 1][1] = r[3];
            }
#pragma unroll
            for (int mt = 0; mt < 4; mt++)
#pragma unroll
                for (int nt = 0; nt < 8; nt++)
                    mma_f16(acc[mt][nt], a[mt], bf[nt]);
        }
    }

    // ---------------- epilogues ----------------
    if (OM == OM_HALF) {
        __half* C = (__half*)Cb;
#pragma unroll
        for (int mt = 0; mt < 4; mt++) {
#pragma unroll
            for (int nt = 0; nt < 8; nt++) {
                int row = bm + wm * 64 + mt * 16 + (lane >> 2);
                int col = bn + wn * 64 + nt * 8 + ((lane & 3) << 1);
                __half2 h0 = __float22half2_rn(make_float2(acc[mt][nt][0], acc[mt][nt][1]));
                __half2 h1 = __float22half2_rn(make_float2(acc[mt][nt][2], acc[mt][nt][3]));
                *reinterpret_cast<__half2*>(C + (long long)row * ldc + col) = h0;
                *reinterpret_cast<__half2*>(C + (long long)(row + 8) * ldc + col) = h1;
            }
        }
    } else if (OM == OM_F32A || OM == OM_F32RES) {
        float* C = (float*)Cb;
#pragma unroll
        for (int mt = 0; mt < 4; mt++) {
#pragma unroll
            for (int nt = 0; nt < 8; nt++) {
                int row = bm + wm * 64 + mt * 16 + (lane >> 2);
                int col = bn + wn * 64 + nt * 8 + ((lane & 3) << 1);
                if (col < N) {
                    if (row < M) {
                        long long i0 = (long long)row * ldc + col;
                        float2 v;
                        v.x = alpha * acc[mt][nt][0];
                        v.y = alpha * acc[mt][nt][1];
                        if (OM == OM_F32RES) { v.x += D[i0]; v.y += D[i0 + 1]; }
                        *reinterpret_cast<float2*>(C + i0) = v;
                    }
                    if (row + 8 < M) {
                        long long i1 = (long long)(row + 8) * ldc + col;
                        float2 v;
                        v.x = alpha * acc[mt][nt][2];
                        v.y = alpha * acc[mt][nt][3];
                        if (OM == OM_F32RES) { v.x += D[i1]; v.y += D[i1 + 1]; }
                        *reinterpret_cast<float2*>(C + i1) = v;
                    }
                }
            }
        }
    } else {   // OM_TRANS: scatter C[b][n][m%FEAT] as fp16 via smem staging
        float* Cs = reinterpret_cast<float*>(smem);
        __half* Ch = (__half*)Cb;
        __syncthreads();
#pragma unroll
        for (int mt = 0; mt < 4; mt++) {
#pragma unroll
            for (int nt = 0; nt < 8; nt++) {
                int nl = wn * 64 + nt * 8 + ((lane & 3) << 1);
                int m0 = wm * 64 + mt * 16 + (lane >> 2);
                Cs[nl * 132 + m0]           = acc[mt][nt][0];
                Cs[(nl + 1) * 132 + m0]     = acc[mt][nt][1];
                Cs[nl * 132 + m0 + 8]       = acc[mt][nt][2];
                Cs[(nl + 1) * 132 + m0 + 8] = acc[mt][nt][3];
            }
        }
        __syncthreads();
#pragma unroll
        for (int it = 0; it < 32; it++) {
            int linear = tid + it * 128;
            int row = linear >> 5;          // local n 0..127
            int c4  = linear & 31;          // 4-float group along m
            int n_g = bn + row;
            int m_g = bm + c4 * 4;          // flat m
            int bb  = m_g / FEAT;
            int mm  = m_g - bb * FEAT;
            float4 v = *reinterpret_cast<const float4*>(&Cs[row * 132 + c4 * 4]);
            __half2 h0 = __float22half2_rn(make_float2(v.x, v.y));
            __half2 h1 = __float22half2_rn(make_float2(v.z, v.w));
            __half2* dst = reinterpret_cast<__half2*>(
                Ch + (long long)bb * sCb + (long long)n_g * ldc + mm);
            dst[0] = h0; dst[1] = h1;
        }
    }
}

// ---------------- fused persistent QKV ----------------
#define QKV_TILES_PER_OP 1280
#define QKV_NTILES 3840

__global__ __launch_bounds__(128, 2)
void qkv_kernel(const __half* __restrict__ qryh, const __half* __restrict__ suph,
                const __half* __restrict__ wq, const __half* __restrict__ wk,
                const __half* __restrict__ wv,
                __half* __restrict__ qT, __half* __restrict__ kT, __half* __restrict__ vN)
{
    extern __shared__ char smem[];
    const uint32_t sb = smem_u32(smem);
    const long long sX = (long long)FEAT * NPTS;   // 655360 halfs per batch (vN)

    for (int t = blockIdx.x; t < QKV_NTILES; t += gridDim.x) {
        int op = t / QKV_TILES_PER_OP;
        int r  = t - op * QKV_TILES_PER_OP;
        int bm = (r >> 4) * 128;
        int bn = (r & 15) * 128;
        __syncthreads();
        if (op == 0) {
            run_tile_h<OM_HALF>(suph, wq, (char*)qT, nullptr,
                                NB * FEAT, 2048, 2048, 2048, 2048, 2048, 0,
                                bm, bn, 1.f, sb, smem);
        } else if (op == 1) {
            run_tile_h<OM_HALF>(qryh, wk, (char*)kT, nullptr,
                                NB * FEAT, 2048, 2048, 2048, 2048, 2048, 0,
                                bm, bn, 1.f, sb, smem);
        } else {
            run_tile_h<OM_TRANS>(qryh, wv, (char*)vN, nullptr,
                                 NB * FEAT, 2048, 2048, 2048, 2048, 320, sX,
                                 bm, bn, 1.f, sb, smem);
        }
    }
}

// ---------------- generic persistent batched GEMM (fp16 in) ----------------
template<int OM>
__global__ __launch_bounds__(128, 2)
void gemm_h_kernel(const __half* __restrict__ Ag, const __half* __restrict__ Bg,
                   char* __restrict__ Cg, const float* __restrict__ Dg,
                   int M, int N, int K, int lda, int ldb, int ldc,
                   long long sA, long long sB, long long sC, long long sD,
                   float alpha, int ntiles, int tn)
{
    extern __shared__ char smem[];
    const uint32_t sb = smem_u32(smem);
    const int per = ((M + 127) >> 7) * tn;
    const int esz = (OM == OM_HALF || OM == OM_TRANS) ? 2 : 4;

    for (int t = blockIdx.x; t < ntiles; t += gridDim.x) {
        int b = t / per;
        int r = t - b * per;
        int bm = (r / tn) * 128;
        int bn = (r % tn) * 128;
        __syncthreads();
        run_tile_h<OM>(Ag + (long long)b * sA, Bg + (long long)b * sB,
                       Cg + (long long)b * sC * esz,
                       Dg ? (Dg + (long long)b * sD) : nullptr,
                       M, N, K, lda, ldb, ldc, 0, bm, bn, alpha, sb, smem);
    }
}

// ---------------- convert / softmax / layernorm ----------------
__global__ __launch_bounds__(256) void f2h_kernel(const float* __restrict__ in,
                                                  __half* __restrict__ out, int n4)
{
    int i = blockIdx.x * 256 + threadIdx.x;
    if (i < n4) {
        float4 v = reinterpret_cast<const float4*>(in)[i];
        __half2 h0 = __float22half2_rn(make_float2(v.x, v.y));
        __half2 h1 = __float22half2_rn(make_float2(v.z, v.w));
        reinterpret_cast<__half2*>(out)[2 * i]     = h0;
        reinterpret_cast<__half2*>(out)[2 * i + 1] = h1;
    }
}

__global__ __launch_bounds__(256) void softmax_kernel(const float* __restrict__ attn,
                                                      __half* __restrict__ probs)
{
    __shared__ float red[256];
    const int tid = threadIdx.x;
    const long long ro = ((long long)blockIdx.y * FEAT + blockIdx.x) * FEAT;
    const float* row = attn + ro;
    float v0 = row[tid];
    float v1 = (tid < FEAT - 256) ? row[tid + 256] : -1e30f;
    red[tid] = fmaxf(v0, v1);
    __syncthreads();
#pragma unroll
    for (int s = 128; s > 0; s >>= 1) {
        if (tid < s) red[tid] = fmaxf(red[tid], red[tid + s]);
        __syncthreads();
    }
    float m = red[0];
    __syncthreads();
    float e0 = expf(v0 - m);
    float e1 = (tid < FEAT - 256) ? expf(v1 - m) : 0.f;
    red[tid] = e0 + e1;
    __syncthreads();
#pragma unroll
    for (int s = 128; s > 0; s >>= 1) {
        if (tid < s) red[tid] += red[tid + s];
        __syncthreads();
    }
    float inv = 1.f / red[0];
    __half* orow = probs + ro;
    orow[tid] = __float2half(e0 * inv);
    if (tid < FEAT - 256) orow[tid + 256] = __float2half(e1 * inv);
}

__global__ __launch_bounds__(256) void ln_kernel(const float* __restrict__ tp,
                                                 const float* __restrict__ gamma,
                                                 const float* __restrict__ beta,
                                                 float* __restrict__ out)
{
    const int b = blockIdx.y;
    const int o = blockIdx.x * 256 + threadIdx.x;
    const float* base = tp + (long long)b * (FEAT * NPTS) + o;
    float s = 0.f, s2 = 0.f;
#pragma unroll 4
    for (int l = 0; l < FEAT; l++) {
        float v = base[(long long)l * NPTS];
        s += v;
        s2 += v * v;
    }
    const float inv = 1.f / FEAT;
    float mu = s * inv;
    float var = s2 * inv - mu * mu;
    float rstd = rsqrtf(var + 1e-5f);
    float* ob = out + (long long)b * (FEAT * NPTS) + o;
#pragma unroll 4
    for (int l = 0; l < FEAT; l++) {
        float v = base[(long long)l * NPTS];
        ob[(long long)l * NPTS] = (v - mu) * rstd * gamma[l] + beta[l];
    }
}

// ---------------- launch ----------------
extern "C" void kernel_launch(void* const* d_in, const int* in_sizes, int n_in,
                              void* d_out, int out_size)
{
    const float* query   = (const float*)d_in[0];
    const float* support = (const float*)d_in[1];
    const float* Wq      = (const float*)d_in[2];
    const float* Wk      = (const float*)d_in[3];
    const float* Wv      = (const float*)d_in[4];
    const float* gamma   = (const float*)d_in[5];
    const float* beta    = (const float*)d_in[6];
    float* out = (float*)d_out;

    void* sp = nullptr;
    cudaGetSymbolAddress(&sp, g_scratch);
    char* S = (char*)sp;
    __half* suph = (__half*)(S + O_SUPH);
    __half* qryh = (__half*)(S + O_QRYH);
    __half* wqh  = (__half*)(S + O_WQH);
    __half* wkh  = (__half*)(S + O_WKH);
    __half* wvh  = (__half*)(S + O_WVH);
    __half* qT   = (__half*)(S + O_QTH);
    __half* kT   = (__half*)(S + O_KTH);
    __half* vN   = (__half*)(S + O_VNH);
    float*  atf  = (float*)(S + O_ATF);
    __half* prh  = (__half*)(S + O_PRH);
    float*  tpf  = (float*)(S + O_TMPF);

    const long long sXh = (long long)FEAT * NPTS;     // 655360 (halfs)
    const long long sAt = (long long)FEAT * FEAT;     // 102400

    static bool attr_set = false;
    if (!attr_set) {
        cudaFuncSetAttribute(qkv_kernel,
                             cudaFuncAttributeMaxDynamicSharedMemorySize, SMEM_TOTAL_BYTES);
        cudaFuncSetAttribute(gemm_h_kernel<OM_F32A>,
                             cudaFuncAttributeMaxDynamicSharedMemorySize, SMEM_TOTAL_BYTES);
        cudaFuncSetAttribute(gemm_h_kernel<OM_F32RES>,
                             cudaFuncAttributeMaxDynamicSharedMemorySize, SMEM_TOTAL_BYTES);
        attr_set = true;
    }

    const size_t smb = SMEM_TOTAL_BYTES;
    const float alpha = 1.0f / sqrtf((float)FEAT);
    const int nX4 = NB * FEAT * NPTS / 4;   // 5242880
    const int nW4 = NPTS * NPTS / 4;        // 1048576

    // fp32 -> fp16 conversions
    f2h_kernel<<<nX4 / 256, 256>>>(support, suph, nX4);
    f2h_kernel<<<nX4 / 256, 256>>>(query, qryh, nX4);
    f2h_kernel<<<nW4 / 256, 256>>>(Wq, wqh, nW4);
    f2h_kernel<<<nW4 / 256, 256>>>(Wk, wkh, nW4);
    f2h_kernel<<<nW4 / 256, 256>>>(Wv, wvh, nW4);

    // fused persistent QKV (flat 10240x2048x2048), vN transposed scatter
    qkv_kernel<<<296, 128, smb>>>(qryh, suph, wqh, wkh, wvh, qT, kT, vN);
    // attn logits fp32: M=N=320, K=2048
    gemm_h_kernel<OM_F32A><<<288, 128, smb>>>(
        qT, kT, (char*)atf, nullptr, 320, 320, 2048, 2048, 2048, 320,
        sXh, sXh, sAt, 0, alpha, 288, 3);
    // softmax -> fp16 probs
    softmax_kernel<<<dim3(FEAT, NB), 256>>>(atf, prh);
    // AV + residual: M=320, N=2048, K=320
    gemm_h_kernel<OM_F32RES><<<296, 128, smb>>>(
        prh, vN, (char*)tpf, query, 320, 2048, 320, 320, 320, 2048,
        sAt, sXh, sXh, sXh, 1.f, 1536, 16);
    // LayerNorm over l (FEAT)
    ln_kernel<<<dim3(NPTS / 256, NB), 256>>>(tpf, gamma, beta, out);
}

// round 8
// speedup vs baseline: 3.2356x; 1.4952x over previous
#include <cuda_runtime.h>
#include <cuda_fp16.h>
#include <cstdint>
#include <cmath>

#define NB 32
#define FEAT 320
#define NPTS 2048

static __device__ float g_scratch[87162880];   // 348 MB

// byte offsets into scratch
#define O_SUPH 0LL
#define O_QRYH 41943040LL
#define O_WQH  83886080LL
#define O_WKH  92274688LL
#define O_WVH  100663296LL
#define O_QTH  109051904LL
#define O_KTH  150994944LL
#define O_VNH  192937984LL
#define O_ATF  234881024LL
#define O_PRH  247988224LL
#define O_TMPF 254541824LL

#define STAGE_BYTES 32768          // A 16KB + B 16KB (fp16, BK=64)
#define SMEM_TOTAL_BYTES (3 * STAGE_BYTES)

#define OM_HALF   0
#define OM_TRANS  1
#define OM_F32A   2
#define OM_F32RES 3

// ---------------- PTX helpers ----------------
__device__ __forceinline__ uint32_t smem_u32(const void* p) {
    uint32_t a;
    asm("{ .reg .u64 t; cvta.to.shared.u64 t, %1; cvt.u32.u64 %0, t; }" : "=r"(a) : "l"(p));
    return a;
}

__device__ __forceinline__ void mma_f16(float* d, const uint32_t* a, const uint32_t* b) {
    asm volatile(
        "mma.sync.aligned.m16n8k16.row.col.f32.f16.f16.f32 "
        "{%0,%1,%2,%3}, {%4,%5,%6,%7}, {%8,%9}, {%0,%1,%2,%3};"
        : "+f"(d[0]), "+f"(d[1]), "+f"(d[2]), "+f"(d[3])
        : "r"(a[0]), "r"(a[1]), "r"(a[2]), "r"(a[3]), "r"(b[0]), "r"(b[1]));
}

__device__ __forceinline__ void ldsm4(uint32_t* r, uint32_t addr) {
    asm volatile("ldmatrix.sync.aligned.m8n8.x4.shared.b16 {%0,%1,%2,%3}, [%4];"
                 : "=r"(r[0]), "=r"(r[1]), "=r"(r[2]), "=r"(r[3]) : "r"(addr));
}

__device__ __forceinline__ void cpasync16(uint32_t dst, const void* src, bool pred) {
    int sz = pred ? 16 : 0;
    asm volatile("cp.async.cg.shared.global [%0], [%1], 16, %2;"
                 :: "r"(dst), "l"(src), "r"(sz) : "memory");
}
#define CP_COMMIT() asm volatile("cp.async.commit_group;" ::: "memory")
#define CP_WAIT1()  asm volatile("cp.async.wait_group 1;" ::: "memory")

// ---------------- fp16 tile core (register-pipelined) ----------------
// One 128x128 tile of C = alpha*A[M,K]*B[N,K]^T (+D). A,B fp16 K-contiguous.
// BK=64, 3-stage cp.async smem pipeline + 2-stage register fragment pipeline,
// 128 threads, warps 2x2, warp tile 64x64, mma m16n8k16.
template<int OM>
__device__ __forceinline__ void run_tile_h(
    const __half* __restrict__ A, const __half* __restrict__ B,
    char* __restrict__ Cb, const float* __restrict__ D,
    int M, int N, int K, int lda, int ldb, int ldc, long long sCb,
    int bm, int bn, float alpha, uint32_t sb, char* smem)
{
    const int tid  = threadIdx.x;
    const int lane = tid & 31;
    const int warp = tid >> 5;
    const int wm = warp & 1;
    const int wn = warp >> 1;

    const int r0  = tid >> 3;          // 0..15
    const int seg = tid & 7;
    const uint32_t xorterm = (uint32_t)((seg ^ (r0 & 7)) << 4);

    // ldmatrix lane->address decomposition
    const int mrowA = ((lane >> 3) & 1) * 8 + (lane & 7);
    const int khA   = lane >> 4;              // 0/1
    const int nrowB = (lane >> 4) * 8 + (lane & 7);
    const int khB   = (lane >> 3) & 1;
    uint32_t offA[4], phA[4], offB[4], phB[4];
#pragma unroll
    for (int mt = 0; mt < 4; mt++) {
        int rowA = wm * 64 + mt * 16 + mrowA;
        offA[mt] = (uint32_t)(rowA * 128);
        phA[mt]  = (uint32_t)(rowA & 7);
    }
#pragma unroll
    for (int np = 0; np < 4; np++) {
        int rowB = wn * 64 + np * 16 + nrowB;
        offB[np] = (uint32_t)(rowB * 128);
        phB[np]  = (uint32_t)(rowB & 7);
    }

    float acc[4][8][4];
#pragma unroll
    for (int i = 0; i < 4; i++)
#pragma unroll
        for (int j = 0; j < 8; j++)
#pragma unroll
            for (int r = 0; r < 4; r++) acc[i][j][r] = 0.f;

    const int NC = K >> 6;   // BK=64

    auto ISSUE = [&](int c) {
        const int k0 = c << 6;
        const uint32_t aB = sb + (uint32_t)((c % 3) * STAGE_BYTES);
        const uint32_t bB = aB + 16384;
#pragma unroll
        for (int i = 0; i < 8; i++) {
            int r = r0 + 16 * i;
            int gr = bm + r;
            bool p = gr < M;
            cpasync16(aB + (uint32_t)(r * 128) + xorterm,
                      A + (long long)(p ? gr : 0) * lda + k0 + seg * 8, p);
        }
#pragma unroll
        for (int i = 0; i < 8; i++) {
            int r = r0 + 16 * i;
            int gn = bn + r;
            bool p = gn < N;
            cpasync16(bB + (uint32_t)(r * 128) + xorterm,
                      B + (long long)(p ? gn : 0) * ldb + k0 + seg * 8, p);
        }
        CP_COMMIT();
    };

    // 2-stage register fragment pipeline
    uint32_t afr[2][4][4];
    uint32_t bfr[2][8][2];

    ISSUE(0);
    ISSUE(1);

    for (int c = 0; c < NC; c++) {
        CP_WAIT1();
        __syncthreads();

        const uint32_t aB = sb + (uint32_t)((c % 3) * STAGE_BYTES);
        const uint32_t bB = aB + 16384;

        // preload ks=0 fragments into buffer 0
        {
            const uint32_t s16 = (uint32_t)khA;
#pragma unroll
            for (int mt = 0; mt < 4; mt++)
                ldsm4(afr[0][mt], aB + offA[mt] + ((s16 ^ phA[mt]) << 4));
        }
        {
            const uint32_t s16 = (uint32_t)khB;
#pragma unroll
            for (int np = 0; np < 4; np++) {
                uint32_t r[4];
                ldsm4(r, bB + offB[np] + ((s16 ^ phB[np]) << 4));
                bfr[0][2 * np][0] = r[0];     bfr[0][2 * np][1] = r[1];
                bfr[0][2 * np + 1][0] = r[2]; bfr[0][2 * np + 1][1] = r[3];
            }
        }

        if (c + 2 < NC) ISSUE(c + 2);
        else CP_COMMIT();

#pragma unroll
        for (int ks = 0; ks < 4; ks++) {
            const int cur = ks & 1;
            const int nxt = cur ^ 1;
            if (ks < 3) {
                // prefetch fragments for ks+1 (overlaps with mma below)
                const uint32_t sA16 = (uint32_t)(2 * (ks + 1) + khA);
#pragma unroll
                for (int mt = 0; mt < 4; mt++)
                    ldsm4(afr[nxt][mt], aB + offA[mt] + ((sA16 ^ phA[mt]) << 4));
                const uint32_t sB16 = (uint32_t)(2 * (ks + 1) + khB);
#pragma unroll
                for (int np = 0; np < 4; np++) {
                    uint32_t r[4];
                    ldsm4(r, bB + offB[np] + ((sB16 ^ phB[np]) << 4));
                    bfr[nxt][2 * np][0] = r[0];     bfr[nxt][2 * np][1] = r[1];
                    bfr[nxt][2 * np + 1][0] = r[2]; bfr[nxt][2 * np + 1][1] = r[3];
                }
            }
#pragma unroll
            for (int mt = 0; mt < 4; mt++)
#pragma unroll
                for (int nt = 0; nt < 8; nt++)
                    mma_f16(acc[mt][nt], afr[cur][mt], bfr[cur][nt]);
        }
    }

    // ---------------- epilogues ----------------
    if (OM == OM_HALF) {
        __half* C = (__half*)Cb;
#pragma unroll
        for (int mt = 0; mt < 4; mt++) {
#pragma unroll
            for (int nt = 0; nt < 8; nt++) {
                int row = bm + wm * 64 + mt * 16 + (lane >> 2);
                int col = bn + wn * 64 + nt * 8 + ((lane & 3) << 1);
                __half2 h0 = __float22half2_rn(make_float2(acc[mt][nt][0], acc[mt][nt][1]));
                __half2 h1 = __float22half2_rn(make_float2(acc[mt][nt][2], acc[mt][nt][3]));
                *reinterpret_cast<__half2*>(C + (long long)row * ldc + col) = h0;
                *reinterpret_cast<__half2*>(C + (long long)(row + 8) * ldc + col) = h1;
            }
        }
    } else if (OM == OM_F32A || OM == OM_F32RES) {
        float* C = (float*)Cb;
#pragma unroll
        for (int mt = 0; mt < 4; mt++) {
#pragma unroll
            for (int nt = 0; nt < 8; nt++) {
                int row = bm + wm * 64 + mt * 16 + (lane >> 2);
                int col = bn + wn * 64 + nt * 8 + ((lane & 3) << 1);
                if (col < N) {
                    if (row < M) {
                        long long i0 = (long long)row * ldc + col;
                        float2 v;
                        v.x = alpha * acc[mt][nt][0];
                        v.y = alpha * acc[mt][nt][1];
                        if (OM == OM_F32RES) { v.x += D[i0]; v.y += D[i0 + 1]; }
                        *reinterpret_cast<float2*>(C + i0) = v;
                    }
                    if (row + 8 < M) {
                        long long i1 = (long long)(row + 8) * ldc + col;
                        float2 v;
                        v.x = alpha * acc[mt][nt][2];
                        v.y = alpha * acc[mt][nt][3];
                        if (OM == OM_F32RES) { v.x += D[i1]; v.y += D[i1 + 1]; }
                        *reinterpret_cast<float2*>(C + i1) = v;
                    }
                }
            }
        }
    } else {   // OM_TRANS: scatter C[b][n][m%FEAT] as fp16 via smem staging
        float* Cs = reinterpret_cast<float*>(smem);
        __half* Ch = (__half*)Cb;
        __syncthreads();
#pragma unroll
        for (int mt = 0; mt < 4; mt++) {
#pragma unroll
            for (int nt = 0; nt < 8; nt++) {
                int nl = wn * 64 + nt * 8 + ((lane & 3) << 1);
                int m0 = wm * 64 + mt * 16 + (lane >> 2);
                Cs[nl * 132 + m0]           = acc[mt][nt][0];
                Cs[(nl + 1) * 132 + m0]     = acc[mt][nt][1];
                Cs[nl * 132 + m0 + 8]       = acc[mt][nt][2];
                Cs[(nl + 1) * 132 + m0 + 8] = acc[mt][nt][3];
            }
        }
        __syncthreads();
#pragma unroll
        for (int it = 0; it < 32; it++) {
            int linear = tid + it * 128;
            int row = linear >> 5;          // local n 0..127
            int c4  = linear & 31;          // 4-float group along m
            int n_g = bn + row;
            int m_g = bm + c4 * 4;          // flat m
            int bb  = m_g / FEAT;
            int mm  = m_g - bb * FEAT;
            float4 v = *reinterpret_cast<const float4*>(&Cs[row * 132 + c4 * 4]);
            __half2 h0 = __float22half2_rn(make_float2(v.x, v.y));
            __half2 h1 = __float22half2_rn(make_float2(v.z, v.w));
            __half2* dst = reinterpret_cast<__half2*>(
                Ch + (long long)bb * sCb + (long long)n_g * ldc + mm);
            dst[0] = h0; dst[1] = h1;
        }
    }
}

// ---------------- fused persistent QKV ----------------
#define QKV_TILES_PER_OP 1280
#define QKV_NTILES 3840

__global__ __launch_bounds__(128, 2)
void qkv_kernel(const __half* __restrict__ qryh, const __half* __restrict__ suph,
                const __half* __restrict__ wq, const __half* __restrict__ wk,
                const __half* __restrict__ wv,
                __half* __restrict__ qT, __half* __restrict__ kT, __half* __restrict__ vN)
{
    extern __shared__ char smem[];
    const uint32_t sb = smem_u32(smem);
    const long long sX = (long long)FEAT * NPTS;   // 655360 halfs per batch (vN)

    for (int t = blockIdx.x; t < QKV_NTILES; t += gridDim.x) {
        int op = t / QKV_TILES_PER_OP;
        int r  = t - op * QKV_TILES_PER_OP;
        int bm = (r >> 4) * 128;
        int bn = (r & 15) * 128;
        __syncthreads();
        if (op == 0) {
            run_tile_h<OM_HALF>(suph, wq, (char*)qT, nullptr,
                                NB * FEAT, 2048, 2048, 2048, 2048, 2048, 0,
                                bm, bn, 1.f, sb, smem);
        } else if (op == 1) {
            run_tile_h<OM_HALF>(qryh, wk, (char*)kT, nullptr,
                                NB * FEAT, 2048, 2048, 2048, 2048, 2048, 0,
                                bm, bn, 1.f, sb, smem);
        } else {
            run_tile_h<OM_TRANS>(qryh, wv, (char*)vN, nullptr,
                                 NB * FEAT, 2048, 2048, 2048, 2048, 320, sX,
                                 bm, bn, 1.f, sb, smem);
        }
    }
}

// ---------------- generic persistent batched GEMM (fp16 in) ----------------
template<int OM>
__global__ __launch_bounds__(128, 2)
void gemm_h_kernel(const __half* __restrict__ Ag, const __half* __restrict__ Bg,
                   char* __restrict__ Cg, const float* __restrict__ Dg,
                   int M, int N, int K, int lda, int ldb, int ldc,
                   long long sA, long long sB, long long sC, long long sD,
                   float alpha, int ntiles, int tn)
{
    extern __shared__ char smem[];
    const uint32_t sb = smem_u32(smem);
    const int per = ((M + 127) >> 7) * tn;
    const int esz = (OM == OM_HALF || OM == OM_TRANS) ? 2 : 4;

    for (int t = blockIdx.x; t < ntiles; t += gridDim.x) {
        int b = t / per;
        int r = t - b * per;
        int bm = (r / tn) * 128;
        int bn = (r % tn) * 128;
        __syncthreads();
        run_tile_h<OM>(Ag + (long long)b * sA, Bg + (long long)b * sB,
                       Cg + (long long)b * sC * esz,
                       Dg ? (Dg + (long long)b * sD) : nullptr,
                       M, N, K, lda, ldb, ldc, 0, bm, bn, alpha, sb, smem);
    }
}

// ---------------- convert / softmax / layernorm ----------------
__global__ __launch_bounds__(256) void f2h_kernel(const float* __restrict__ in,
                                                  __half* __restrict__ out, int n4)
{
    int i = blockIdx.x * 256 + threadIdx.x;
    if (i < n4) {
        float4 v = reinterpret_cast<const float4*>(in)[i];
        __half2 h0 = __float22half2_rn(make_float2(v.x, v.y));
        __half2 h1 = __float22half2_rn(make_float2(v.z, v.w));
        reinterpret_cast<__half2*>(out)[2 * i]     = h0;
        reinterpret_cast<__half2*>(out)[2 * i + 1] = h1;
    }
}

__global__ __launch_bounds__(256) void softmax_kernel(const float* __restrict__ attn,
                                                      __half* __restrict__ probs)
{
    __shared__ float red[256];
    const int tid = threadIdx.x;
    const long long ro = ((long long)blockIdx.y * FEAT + blockIdx.x) * FEAT;
    const float* row = attn + ro;
    float v0 = row[tid];
    float v1 = (tid < FEAT - 256) ? row[tid + 256] : -1e30f;
    red[tid] = fmaxf(v0, v1);
    __syncthreads();
#pragma unroll
    for (int s = 128; s > 0; s >>= 1) {
        if (tid < s) red[tid] = fmaxf(red[tid], red[tid + s]);
        __syncthreads();
    }
    float m = red[0];
    __syncthreads();
    float e0 = expf(v0 - m);
    float e1 = (tid < FEAT - 256) ? expf(v1 - m) : 0.f;
    red[tid] = e0 + e1;
    __syncthreads();
#pragma unroll
    for (int s = 128; s > 0; s >>= 1) {
        if (tid < s) red[tid] += red[tid + s];
        __syncthreads();
    }
    float inv = 1.f / red[0];
    __half* orow = probs + ro;
    orow[tid] = __float2half(e0 * inv);
    if (tid < FEAT - 256) orow[tid + 256] = __float2half(e1 * inv);
}

__global__ __launch_bounds__(256) void ln_kernel(const float* __restrict__ tp,
                                                 const float* __restrict__ gamma,
                                                 const float* __restrict__ beta,
                                                 float* __restrict__ out)
{
    const int b = blockIdx.y;
    const int o = blockIdx.x * 256 + threadIdx.x;
    const float* base = tp + (long long)b * (FEAT * NPTS) + o;
    float s = 0.f, s2 = 0.f;
#pragma unroll 4
    for (int l = 0; l < FEAT; l++) {
        float v = base[(long long)l * NPTS];
        s += v;
        s2 += v * v;
    }
    const float inv = 1.f / FEAT;
    float mu = s * inv;
    float var = s2 * inv - mu * mu;
    float rstd = rsqrtf(var + 1e-5f);
    float* ob = out + (long long)b * (FEAT * NPTS) + o;
#pragma unroll 4
    for (int l = 0; l < FEAT; l++) {
        float v = base[(long long)l * NPTS];
        ob[(long long)l * NPTS] = (v - mu) * rstd * gamma[l] + beta[l];
    }
}

// ---------------- launch ----------------
extern "C" void kernel_launch(void* const* d_in, const int* in_sizes, int n_in,
                              void* d_out, int out_size)
{
    const float* query   = (const float*)d_in[0];
    const float* support = (const float*)d_in[1];
    const float* Wq      = (const float*)d_in[2];
    const float* Wk      = (const float*)d_in[3];
    const float* Wv      = (const float*)d_in[4];
    const float* gamma   = (const float*)d_in[5];
    const float* beta    = (const float*)d_in[6];
    float* out = (float*)d_out;

    void* sp = nullptr;
    cudaGetSymbolAddress(&sp, g_scratch);
    char* S = (char*)sp;
    __half* suph = (__half*)(S + O_SUPH);
    __half* qryh = (__half*)(S + O_QRYH);
    __half* wqh  = (__half*)(S + O_WQH);
    __half* wkh  = (__half*)(S + O_WKH);
    __half* wvh  = (__half*)(S + O_WVH);
    __half* qT   = (__half*)(S + O_QTH);
    __half* kT   = (__half*)(S + O_KTH);
    __half* vN   = (__half*)(S + O_VNH);
    float*  atf  = (float*)(S + O_ATF);
    __half* prh  = (__half*)(S + O_PRH);
    float*  tpf  = (float*)(S + O_TMPF);

    const long long sXh = (long long)FEAT * NPTS;     // 655360 (halfs)
    const long long sAt = (long long)FEAT * FEAT;     // 102400

    static bool attr_set = false;
    if (!attr_set) {
        cudaFuncSetAttribute(qkv_kernel,
                             cudaFuncAttributeMaxDynamicSharedMemorySize, SMEM_TOTAL_BYTES);
        cudaFuncSetAttribute(gemm_h_kernel<OM_F32A>,
                             cudaFuncAttributeMaxDynamicSharedMemorySize, SMEM_TOTAL_BYTES);
        cudaFuncSetAttribute(gemm_h_kernel<OM_F32RES>,
                             cudaFuncAttributeMaxDynamicSharedMemorySize, SMEM_TOTAL_BYTES);
        attr_set = true;
    }

    const size_t smb = SMEM_TOTAL_BYTES;
    const float alpha = 1.0f / sqrtf((float)FEAT);
    const int nX4 = NB * FEAT * NPTS / 4;   // 5242880
    const int nW4 = NPTS * NPTS / 4;        // 1048576

    // fp32 -> fp16 conversions
    f2h_kernel<<<nX4 / 256, 256>>>(support, suph, nX4);
    f2h_kernel<<<nX4 / 256, 256>>>(query, qryh, nX4);
    f2h_kernel<<<nW4 / 256, 256>>>(Wq, wqh, nW4);
    f2h_kernel<<<nW4 / 256, 256>>>(Wk, wkh, nW4);
    f2h_kernel<<<nW4 / 256, 256>>>(Wv, wvh, nW4);

    // fused persistent QKV (flat 10240x2048x2048), vN transposed scatter
    qkv_kernel<<<296, 128, smb>>>(qryh, suph, wqh, wkh, wvh, qT, kT, vN);
    // attn logits fp32: M=N=320, K=2048
    gemm_h_kernel<OM_F32A><<<288, 128, smb>>>(
        qT, kT, (char*)atf, nullptr, 320, 320, 2048, 2048, 2048, 320,
        sXh, sXh, sAt, 0, alpha, 288, 3);
    // softmax -> fp16 probs
    softmax_kernel<<<dim3(FEAT, NB), 256>>>(atf, prh);
    // AV + residual: M=320, N=2048, K=320
    gemm_h_kernel<OM_F32RES><<<296, 128, smb>>>(
        prh, vN, (char*)tpf, query, 320, 2048, 320, 320, 320, 2048,
        sAt, sXh, sXh, sXh, 1.f, 1536, 16);
    // LayerNorm over l (FEAT)
    ln_kernel<<<dim3(NPTS / 256, NB), 256>>>(tpf, gamma, beta, out);
}